// round 12
// baseline (speedup 1.0000x reference)
#include <cuda_runtime.h>
#include <cuda_bf16.h>
#include <math.h>
#include <float.h>
#include <stdint.h>

#define NUM_CLASSES 80
#define N_PROP 1000
#define CCH 256
#define ROI 7
#define DFEAT (CCH * ROI * ROI)   // 12544
#define FC 1024
#define NHEAD 401
#define SCORE_THR 0.05f
#define IOU_THR 0.5f
#define MAX_DET 100
#define MAX_RATIO 4.135166556742356f
#define SPLITK 4
#define QA 8.0f      // activation scale into fp8
#define QW 32.0f     // weight scale into fp8
#define QINV (1.0f / 256.0f)

// ---------------- device scratch ----------------
__device__ __nv_bfloat16 g_f0t[200 * 336 * CCH];
__device__ __nv_bfloat16 g_f1t[100 * 168 * CCH];
__device__ __nv_bfloat16 g_f2t[50 * 84 * CCH];
__device__ __nv_bfloat16 g_f3t[25 * 42 * CCH];

__device__ uint8_t g_roi_feats[N_PROP * DFEAT];   // fp8 e4m3, x8
__device__ uint8_t g_h1[N_PROP * FC];             // fp8, x8
__device__ uint8_t g_h2[N_PROP * FC];             // fp8, x8
__device__ uint8_t g_fc1w[FC * DFEAT];            // fp8, x32
__device__ uint8_t g_fc2w[FC * FC];               // fp8, x32
__device__ uint8_t g_headw[NHEAD * FC];           // fp8, x32
__device__ float g_headb[NHEAD];
__device__ float g_part[SPLITK * N_PROP * FC];

__device__ float g_scores80[N_PROP * NUM_CLASSES];
__device__ float g_boxes[N_PROP * NUM_CLASSES * 4];
__device__ float g_sorted_boxes[NUM_CLASSES * N_PROP * 4];

__device__ int g_ncand;
__device__ float g_cand_v[NUM_CLASSES * N_PROP];
__device__ int   g_cand_i[NUM_CLASSES * N_PROP];

// ---------------- fp8 helpers ----------------
__device__ __forceinline__ uint16_t f2e4(float hi, float lo) {
    uint16_t r;
    asm("cvt.rn.satfinite.e4m3x2.f32 %0, %1, %2;" : "=h"(r) : "f"(hi), "f"(lo));
    return r;
}

// ---------------- fused prep: transposes + weight quant + head concat ------
#define PREP_T0 22320
#define PREP_T1 34864
#define PREP_T2 35888
#define PREP_TOTAL 37492

__global__ void prep_kernel(const float* __restrict__ f0,
                            const float* __restrict__ f1,
                            const float* __restrict__ f2,
                            const float* __restrict__ f3,
                            __nv_bfloat16* __restrict__ o0,
                            __nv_bfloat16* __restrict__ o1,
                            __nv_bfloat16* __restrict__ o2,
                            __nv_bfloat16* __restrict__ o3,
                            const float* __restrict__ fc1_w,
                            uint8_t* __restrict__ fc1wq,
                            const float* __restrict__ fc2_w,
                            uint8_t* __restrict__ fc2wq,
                            const float* __restrict__ cls_w,
                            const float* __restrict__ reg_w,
                            const float* __restrict__ cls_b,
                            const float* __restrict__ reg_b,
                            uint8_t* __restrict__ headwq,
                            float* __restrict__ headb) {
    const int b = blockIdx.x;
    const int tid = threadIdx.x;

    if (b < PREP_T0) {
        __shared__ float t[32][33];
        int bt = b >> 3;
        int c0 = (b & 7) * 32;
        const float* in; __nv_bfloat16* out; int HW; int tile;
        if (bt < 2100)      { in = f0; out = o0; HW = 67200; tile = bt; }
        else if (bt < 2625) { in = f1; out = o1; HW = 16800; tile = bt - 2100; }
        else if (bt < 2757) { in = f2; out = o2; HW = 4200;  tile = bt - 2625; }
        else                { in = f3; out = o3; HW = 1050;  tile = bt - 2757; }
        int hw0 = tile * 32;
        int tx = tid & 31, ty = tid >> 5;
        int x = hw0 + tx;
        #pragma unroll
        for (int i = 0; i < 32; i += 8) {
            int c = c0 + ty + i;
            if (x < HW) t[ty + i][tx] = in[(size_t)c * HW + x];
        }
        __syncthreads();
        int co = c0 + tx;
        #pragma unroll
        for (int i = 0; i < 32; i += 8) {
            int xo = hw0 + ty + i;
            if (xo < HW)
                out[(size_t)xo * CCH + co] = __float2bfloat16(t[tx][ty + i]);
        }
    } else if (b < PREP_T1) {
        int i = (b - PREP_T0) * 256 + tid;        // float4 index
        float4 v = ((const float4*)fc1_w)[i];
        uint32_t lo = f2e4(v.y * QW, v.x * QW);
        uint32_t hi = f2e4(v.w * QW, v.z * QW);
        ((uint32_t*)fc1wq)[i] = lo | (hi << 16);
    } else if (b < PREP_T2) {
        int i = (b - PREP_T1) * 256 + tid;
        float4 v = ((const float4*)fc2_w)[i];
        uint32_t lo = f2e4(v.y * QW, v.x * QW);
        uint32_t hi = f2e4(v.w * QW, v.z * QW);
        ((uint32_t*)fc2wq)[i] = lo | (hi << 16);
    } else {
        int i = (b - PREP_T2) * 256 + tid;
        const int total = NHEAD * FC;
        if (i < total) {
            int r = i >> 10, k = i & 1023;
            float v = (r < 81) ? cls_w[r * FC + k] : reg_w[(r - 81) * FC + k];
            headwq[i] = (uint8_t)(f2e4(0.0f, v * QW) & 0xFF);
        }
        if (i < NHEAD) headb[i] = (i < 81) ? cls_b[i] : reg_b[i - 81];
    }
}

// ---------------- RoI Align (bf16 NHWC in, fp8 x8 out) ----------------
__global__ void roi_align_kernel(const __nv_bfloat16* __restrict__ f0,
                                 const __nv_bfloat16* __restrict__ f1,
                                 const __nv_bfloat16* __restrict__ f2,
                                 const __nv_bfloat16* __restrict__ f3,
                                 const float* __restrict__ props,
                                 uint8_t* __restrict__ out) {
    const int n = blockIdx.x;
    const int tid = threadIdx.x;

    __shared__ int sx0[14], sx1[14], sy0[14], sy1[14];
    __shared__ float slx[14], sly[14];
    __shared__ int svx[14], svy[14];

    float px1 = props[n * 4 + 0];
    float py1 = props[n * 4 + 1];
    float px2 = props[n * 4 + 2];
    float py2 = props[n * 4 + 3];
    float w = px2 - px1, h = py2 - py1;
    float sz = sqrtf(fmaxf(w * h, 1e-6f));
    int lvl = (int)floorf(log2f(sz / 56.0f + 1e-6f));
    lvl = lvl < 0 ? 0 : (lvl > 3 ? 3 : lvl);

    const __nv_bfloat16* feat;
    int H, W;
    if (lvl == 0) { feat = f0; H = 200; W = 336; }
    else if (lvl == 1) { feat = f1; H = 100; W = 168; }
    else if (lvl == 2) { feat = f2; H = 50; W = 84; }
    else { feat = f3; H = 25; W = 42; }
    float scale = 1.0f / (float)(4 << lvl);

    if (tid < 14) {
        int i = tid;
        float pt = ((float)i + 0.5f) / 14.0f;
        {
            float xs = px1 * scale - 0.5f + pt * (w * scale);
            float fx = floorf(xs);
            int x0 = (int)fx; x0 = x0 < 0 ? 0 : (x0 > W - 1 ? W - 1 : x0);
            int x1i = x0 + 1; x1i = x1i > W - 1 ? W - 1 : x1i;
            sx0[i] = x0; sx1[i] = x1i;
            slx[i] = xs - fx;
            svx[i] = (xs >= -1.0f && xs <= (float)W) ? 1 : 0;
        }
        {
            float ys = py1 * scale - 0.5f + pt * (h * scale);
            float fy = floorf(ys);
            int y0 = (int)fy; y0 = y0 < 0 ? 0 : (y0 > H - 1 ? H - 1 : y0);
            int y1i = y0 + 1; y1i = y1i > H - 1 ? H - 1 : y1i;
            sy0[i] = y0; sy1[i] = y1i;
            sly[i] = ys - fy;
            svy[i] = (ys >= -1.0f && ys <= (float)H) ? 1 : 0;
        }
    }
    __syncthreads();

    const __nv_bfloat162* feat2 = (const __nv_bfloat162*)feat;
    uint8_t* op0 = out + (size_t)n * DFEAT + (size_t)(2 * tid) * (ROI * ROI);
    uint8_t* op1 = op0 + (ROI * ROI);

    #pragma unroll
    for (int py = 0; py < ROI; py++) {
        #pragma unroll
        for (int px = 0; px < ROI; px++) {
            float acc0 = 0.0f, acc1 = 0.0f;
            #pragma unroll
            for (int sy = 0; sy < 2; sy++) {
                int iy = py * 2 + sy;
                int y0 = sy0[iy], y1v = sy1[iy];
                float ly = sly[iy];
                int vy = svy[iy];
                #pragma unroll
                for (int sxs = 0; sxs < 2; sxs++) {
                    int ix = px * 2 + sxs;
                    if (vy && svx[ix]) {
                        int x0 = sx0[ix], x1v = sx1[ix];
                        float lx = slx[ix];
                        float2 v00 = __bfloat1622float2(feat2[((size_t)(y0 * W + x0) << 7) + tid]);
                        float2 v01 = __bfloat1622float2(feat2[((size_t)(y0 * W + x1v) << 7) + tid]);
                        float2 v10 = __bfloat1622float2(feat2[((size_t)(y1v * W + x0) << 7) + tid]);
                        float2 v11 = __bfloat1622float2(feat2[((size_t)(y1v * W + x1v) << 7) + tid]);
                        float wy0 = 1.0f - ly, wx0 = 1.0f - lx;
                        acc0 += wy0 * (wx0 * v00.x + lx * v01.x) + ly * (wx0 * v10.x + lx * v11.x);
                        acc1 += wy0 * (wx0 * v00.y + lx * v01.y) + ly * (wx0 * v10.y + lx * v11.y);
                    }
                }
            }
            // *0.25 (avg) * QA(8) = *2
            op0[py * ROI + px] = (uint8_t)(f2e4(0.0f, acc0 * 2.0f) & 0xFF);
            op1[py * ROI + px] = (uint8_t)(f2e4(0.0f, acc1 * 2.0f) & 0xFF);
        }
    }
}

// ---------------- pipelined fp8 mma GEMM: cp.async 4-stage + ldmatrix ------
__device__ __forceinline__ void mma16832_e4m3(float* c, const uint32_t* a, const uint32_t* b) {
    asm volatile(
        "mma.sync.aligned.m16n8k32.row.col.f32.e4m3.e4m3.f32 "
        "{%0,%1,%2,%3},{%4,%5,%6,%7},{%8,%9},{%0,%1,%2,%3};"
        : "+f"(c[0]), "+f"(c[1]), "+f"(c[2]), "+f"(c[3])
        : "r"(a[0]), "r"(a[1]), "r"(a[2]), "r"(a[3]), "r"(b[0]), "r"(b[1]));
}

__device__ __forceinline__ void ldmx4(uint32_t* r, uint32_t addr) {
    asm volatile("ldmatrix.sync.aligned.m8n8.x4.shared.b16 {%0,%1,%2,%3}, [%4];"
                 : "=r"(r[0]), "=r"(r[1]), "=r"(r[2]), "=r"(r[3]) : "r"(addr));
}

__device__ __forceinline__ void cp16(uint32_t dst, const void* src, int valid) {
    int sz = valid ? 16 : 0;
    asm volatile("cp.async.cg.shared.global [%0], [%1], 16, %2;"
                 :: "r"(dst), "l"(src), "r"(sz));
}

#define ROWB 80                   // bytes per smem row: 64 data + 16 pad
#define TBK 64                    // fp8 elements per k-tile (=64 bytes)
#define STAGE_B (256 * ROWB)      // A(128 rows) + B(128 rows), bytes
#define NSTAGE 4
#define GEMM_SMEM (NSTAGE * STAGE_B)

__global__ __launch_bounds__(512, 2)
void gemm_fp8_splitk_kernel(const uint8_t* __restrict__ Afull,
                            const uint8_t* __restrict__ Bfull,
                            float* __restrict__ Cpart,
                            int M, int N, int Kc, int lda) {
    extern __shared__ uint8_t smem[];

    const int tid = threadIdx.x;
    const int warp = tid >> 5, lane = tid & 31;
    const int wm = warp >> 2, wn = warp & 3;
    const int g = lane >> 2, tg = lane & 3;
    const int m0 = blockIdx.y * 128, n0 = blockIdx.x * 128;
    const int z = blockIdx.z;

    const uint8_t* A = Afull + (size_t)z * Kc;
    const uint8_t* B = Bfull + (size_t)z * Kc;

    const int row = tid >> 2;            // 0..127
    const int kcB = (tid & 3) * 16;      // byte offset 0,16,32,48

    float acc[2][4][4];
    #pragma unroll
    for (int i = 0; i < 2; i++)
        #pragma unroll
        for (int j = 0; j < 4; j++)
            #pragma unroll
            for (int q = 0; q < 4; q++) acc[i][j][q] = 0.0f;

    const uint32_t smem_u32 = (uint32_t)__cvta_generic_to_shared(smem);
    const uint32_t dA = smem_u32 + (uint32_t)(row * ROWB + kcB);
    const uint32_t dB = dA + (uint32_t)(128 * ROWB);
    const int a_row_l = wm * 32 + (lane & 15);
    const int a_colB = (lane >> 4) * 16;
    const uint32_t aadr = smem_u32 + (uint32_t)(a_row_l * ROWB + a_colB);
    const int b_row_l = wn * 32 + (lane & 7) + ((lane >> 4) << 3);
    const int b_colB = ((lane >> 3) & 1) * 16;
    const uint32_t badr = smem_u32 + (uint32_t)(128 * ROWB + b_row_l * ROWB + b_colB);

    const int ar_ok = (m0 + row) < M;
    const int br_ok = (n0 + row) < N;
    const uint8_t* aSrcBase = A + (size_t)(m0 + row) * lda + kcB;
    const uint8_t* bSrcBase = B + (size_t)(n0 + row) * lda + kcB;

    const int nIter = Kc / TBK;

    cp16(dA, aSrcBase, ar_ok);
    cp16(dB, bSrcBase, br_ok);
    asm volatile("cp.async.commit_group;");
    if (nIter > 1) {
        cp16(dA + STAGE_B, aSrcBase + TBK, ar_ok);
        cp16(dB + STAGE_B, bSrcBase + TBK, br_ok);
    }
    asm volatile("cp.async.commit_group;");
    if (nIter > 2) {
        cp16(dA + 2 * STAGE_B, aSrcBase + 2 * TBK, ar_ok);
        cp16(dB + 2 * STAGE_B, bSrcBase + 2 * TBK, br_ok);
    }
    asm volatile("cp.async.commit_group;");

    int st = 0;
    for (int it = 0; it < nIter; it++) {
        asm volatile("cp.async.wait_group 2;");
        __syncthreads();

        const uint32_t so = (uint32_t)(st * STAGE_B);
        #pragma unroll
        for (int ks = 0; ks < 2; ks++) {
            const uint32_t koff = so + (uint32_t)(ks * 32);   // k32 fp8 = 32 bytes
            uint32_t af[2][4], bfr[2][4];
            ldmx4(af[0], aadr + koff);
            ldmx4(af[1], aadr + koff + (uint32_t)(16 * ROWB));
            ldmx4(bfr[0], badr + koff);
            ldmx4(bfr[1], badr + koff + (uint32_t)(16 * ROWB));
            #pragma unroll
            for (int mt = 0; mt < 2; mt++)
                #pragma unroll
                for (int nt = 0; nt < 4; nt++)
                    mma16832_e4m3(acc[mt][nt], af[mt], &bfr[nt >> 1][(nt & 1) * 2]);
        }

        if (it + 3 < nIter) {
            int st3 = st + 3; if (st3 >= NSTAGE) st3 -= NSTAGE;
            const uint32_t so3 = (uint32_t)(st3 * STAGE_B);
            cp16(dA + so3, aSrcBase + (it + 3) * TBK, ar_ok);
            cp16(dB + so3, bSrcBase + (it + 3) * TBK, br_ok);
        }
        asm volatile("cp.async.commit_group;");

        if (++st == NSTAGE) st = 0;
    }

    float* Cp = Cpart + (size_t)z * M * N;
    #pragma unroll
    for (int mt = 0; mt < 2; mt++) {
        #pragma unroll
        for (int nt = 0; nt < 4; nt++) {
            int n = n0 + wn * 32 + nt * 8 + tg * 2;
            if (n >= N) continue;
            #pragma unroll
            for (int rh = 0; rh < 2; rh++) {
                int m = m0 + wm * 32 + mt * 16 + g + rh * 8;
                if (m >= M) continue;
                Cp[(size_t)m * N + n] = acc[mt][nt][rh * 2 + 0] * QINV;
                if (n + 1 < N) Cp[(size_t)m * N + n + 1] = acc[mt][nt][rh * 2 + 1] * QINV;
            }
        }
    }
}

// ---------------- split-K reduce + bias + relu + fp8(x8) quant -------------
__global__ void reduce_k_kernel(const float* __restrict__ part,
                                const float* __restrict__ bias,
                                uint8_t* __restrict__ out,
                                int M, int N) {
    int i = blockIdx.x * blockDim.x + threadIdx.x;
    int tot = M * N;
    if (i >= tot) return;
    int n = i % N;
    float v = part[i];
    #pragma unroll
    for (int s = 1; s < SPLITK; s++) v += part[(size_t)s * tot + i];
    v += bias[n];
    v = fmaxf(v, 0.0f);
    out[i] = (uint8_t)(f2e4(0.0f, v * QA) & 0xFF);
}

// ---------------- softmax + delta2bbox (reads head partials directly) ------
__global__ void head_kernel(const float* __restrict__ part,
                            const float* __restrict__ headb,
                            const float* __restrict__ props,
                            float* __restrict__ scores80,
                            float* __restrict__ boxes) {
    const int n = blockIdx.x;
    const int tid = threadIdx.x;
    if (n == 0 && tid == 0) g_ncand = 0;

    const int TOT = N_PROP * NHEAD;

    __shared__ float sv[81];
    __shared__ float red[128];

    float v = -FLT_MAX;
    if (tid < 81) {
        v = headb[tid];
        #pragma unroll
        for (int s = 0; s < SPLITK; s++)
            v += part[(size_t)s * TOT + (size_t)n * NHEAD + tid];
        sv[tid] = v;
    }
    red[tid] = v;
    __syncthreads();
    for (int s = 64; s > 0; s >>= 1) {
        if (tid < s) red[tid] = fmaxf(red[tid], red[tid + s]);
        __syncthreads();
    }
    float mx = red[0];
    __syncthreads();
    float e = (tid < 81) ? expf(sv[tid] - mx) : 0.0f;
    red[tid] = e;
    __syncthreads();
    for (int s = 64; s > 0; s >>= 1) {
        if (tid < s) red[tid] += red[tid + s];
        __syncthreads();
    }
    float sum = red[0];

    if (tid < NUM_CLASSES) {
        scores80[n * NUM_CLASSES + tid] = e / sum;

        float rp[4];
        #pragma unroll
        for (int q = 0; q < 4; q++) {
            int idx = 81 + tid * 4 + q;
            float r = headb[idx];
            #pragma unroll
            for (int s = 0; s < SPLITK; s++)
                r += part[(size_t)s * TOT + (size_t)n * NHEAD + idx];
            rp[q] = r;
        }
        float dx = rp[0] * 0.1f;
        float dy = rp[1] * 0.1f;
        float dw = fminf(fmaxf(rp[2] * 0.2f, -MAX_RATIO), MAX_RATIO);
        float dh = fminf(fmaxf(rp[3] * 0.2f, -MAX_RATIO), MAX_RATIO);
        float p0 = props[n * 4 + 0], p1 = props[n * 4 + 1];
        float p2 = props[n * 4 + 2], p3 = props[n * 4 + 3];
        float pcx = (p0 + p2) * 0.5f;
        float pcy = (p1 + p3) * 0.5f;
        float pw = p2 - p0, ph = p3 - p1;
        float gw = pw * expf(dw);
        float gh = ph * expf(dh);
        float gx = pcx + pw * dx;
        float gy = pcy + ph * dy;
        float* bp = boxes + ((size_t)n * NUM_CLASSES + tid) * 4;
        bp[0] = gx - gw * 0.5f;
        bp[1] = gy - gh * 0.5f;
        bp[2] = gx + gw * 0.5f;
        bp[3] = gy + gh * 0.5f;
    }
}

// ---------------- per-class NMS, appends candidates ----------------
__global__ void nms_kernel(const float* __restrict__ scores80,
                           const float* __restrict__ boxesAll,
                           float* __restrict__ sortedBoxes) {
    const int c = blockIdx.x;
    const int tid = threadIdx.x;
    const int NT = 256;

    __shared__ float skey[1024];
    __shared__ int sidx[1024];
    __shared__ float4 sbox[N_PROP];
    __shared__ float sarea[N_PROP];
    __shared__ unsigned char keep[N_PROP];
    __shared__ float redmax[NT];

    float mv = -FLT_MAX;
    for (int j = tid; j < N_PROP; j += NT) {
        float s = scores80[j * NUM_CLASSES + c];
        mv = fmaxf(mv, s);
        skey[j] = s;
    }
    redmax[tid] = mv;
    __syncthreads();
    for (int s = NT / 2; s > 0; s >>= 1) {
        if (tid < s) redmax[tid] = fmaxf(redmax[tid], redmax[tid + s]);
        __syncthreads();
    }
    if (redmax[0] <= SCORE_THR) return;

    for (int j = tid; j < 1024; j += NT) {
        if (j >= N_PROP) skey[j] = -FLT_MAX;
        sidx[j] = j;
    }

    for (int k = 2; k <= 1024; k <<= 1) {
        for (int j = k >> 1; j > 0; j >>= 1) {
            __syncthreads();
            for (int i = tid; i < 1024; i += NT) {
                int ixj = i ^ j;
                if (ixj > i) {
                    float si = skey[i], sx = skey[ixj];
                    int ii = sidx[i], ix = sidx[ixj];
                    bool x_first = (sx > si) || (sx == si && ix < ii);
                    bool up = ((i & k) == 0);
                    if (up ? x_first : !x_first) {
                        skey[i] = sx; skey[ixj] = si;
                        sidx[i] = ix; sidx[ixj] = ii;
                    }
                }
            }
        }
    }
    __syncthreads();

    for (int j = tid; j < N_PROP; j += NT) {
        int oi = sidx[j];
        float4 b = *(const float4*)&boxesAll[((size_t)oi * NUM_CLASSES + c) * 4];
        sbox[j] = b;
        sarea[j] = fmaxf(b.z - b.x, 0.0f) * fmaxf(b.w - b.y, 0.0f);
        keep[j] = (skey[j] > SCORE_THR) ? 1 : 0;
    }
    __syncthreads();

    for (int i = 0; i < N_PROP; i++) {
        if (skey[i] <= SCORE_THR) break;
        __syncthreads();
        if (keep[i]) {
            float4 bi = sbox[i];
            float ai = sarea[i];
            for (int j = i + 1 + tid; j < N_PROP; j += NT) {
                if (!keep[j]) continue;
                float4 bj = sbox[j];
                float iw = fmaxf(fminf(bi.z, bj.z) - fmaxf(bi.x, bj.x), 0.0f);
                float ih = fmaxf(fminf(bi.w, bj.w) - fmaxf(bi.y, bj.y), 0.0f);
                float inter = iw * ih;
                float iou = inter / fmaxf(ai + sarea[j] - inter, 1e-8f);
                if (iou > IOU_THR) keep[j] = 0;
            }
        }
    }
    __syncthreads();

    for (int j = tid; j < N_PROP; j += NT) {
        *(float4*)&sortedBoxes[((size_t)c * N_PROP + j) * 4] = sbox[j];
        if (keep[j]) {
            int p = atomicAdd(&g_ncand, 1);
            g_cand_v[p] = skey[j];
            g_cand_i[p] = c * N_PROP + j;
        }
    }
}

// ---------------- top-k + output assembly ----------------
__global__ void topk_kernel(const float* __restrict__ sortedBoxes,
                            float* __restrict__ out, int out_size) {
    const int tid = threadIdx.x;
    const int NT = 256;
    const int nc = g_ncand;
    const int nsel = nc < MAX_DET ? nc : MAX_DET;

    __shared__ float rv[NT];
    __shared__ int ri[NT];
    __shared__ int rs[NT];
    __shared__ float topv[MAX_DET];
    __shared__ int topi[MAX_DET];

    for (int k = tid; k < MAX_DET; k += NT) { topv[k] = -FLT_MAX; topi[k] = 0; }
    __syncthreads();

    for (int sel = 0; sel < nsel; sel++) {
        float bv = -FLT_MAX;
        int bi = 0x7fffffff, bs = -1;
        for (int j = tid; j < nc; j += NT) {
            float v = g_cand_v[j];
            int fi = g_cand_i[j];
            if (v > bv || (v == bv && fi < bi)) { bv = v; bi = fi; bs = j; }
        }
        rv[tid] = bv; ri[tid] = bi; rs[tid] = bs;
        __syncthreads();
        for (int s = NT / 2; s > 0; s >>= 1) {
            if (tid < s) {
                if (rv[tid + s] > rv[tid] ||
                    (rv[tid + s] == rv[tid] && ri[tid + s] < ri[tid])) {
                    rv[tid] = rv[tid + s]; ri[tid] = ri[tid + s]; rs[tid] = rs[tid + s];
                }
            }
            __syncthreads();
        }
        if (tid == 0) {
            topv[sel] = rv[0];
            topi[sel] = ri[0];
            if (rs[0] >= 0) g_cand_v[rs[0]] = -FLT_MAX;
        }
        __syncthreads();
    }

    if (tid == 0) {
        int nd = 0;
        for (int k = 0; k < MAX_DET; k++)
            if (topv[k] > 0.0f) nd++;
        if (out_size > 0) out[0] = (float)nd;
    }
    __syncthreads();

    for (int k = tid; k < MAX_DET; k += NT) {
        bool valid = topv[k] > 0.0f;
        int oi = topi[k];
        float b0 = 0.f, b1 = 0.f, b2 = 0.f, b3 = 0.f;
        if (valid) {
            const float* bp = &sortedBoxes[(size_t)oi * 4];
            b0 = bp[0]; b1 = bp[1]; b2 = bp[2]; b3 = bp[3];
        }
        if (1 + k * 4 + 3 < out_size) {
            out[1 + k * 4 + 0] = b0;
            out[1 + k * 4 + 1] = b1;
            out[1 + k * 4 + 2] = b2;
            out[1 + k * 4 + 3] = b3;
        }
        if (401 + k < out_size) out[401 + k] = valid ? topv[k] : 0.0f;
        if (501 + k < out_size) out[501 + k] = valid ? (float)(oi / N_PROP) : -1.0f;
    }
    for (int i = 601 + tid; i < out_size; i += NT) out[i] = 0.0f;
}

// ---------------- launch ----------------
extern "C" void kernel_launch(void* const* d_in, const int* in_sizes, int n_in,
                              void* d_out, int out_size) {
    const float* f0 = (const float*)d_in[0];
    const float* f1 = (const float*)d_in[1];
    const float* f2 = (const float*)d_in[2];
    const float* f3 = (const float*)d_in[3];
    const float* props = (const float*)d_in[4];
    const float* fc1_w = (const float*)d_in[5];
    const float* fc1_b = (const float*)d_in[6];
    const float* fc2_w = (const float*)d_in[7];
    const float* fc2_b = (const float*)d_in[8];
    const float* cls_w = (const float*)d_in[9];
    const float* cls_b = (const float*)d_in[10];
    const float* reg_w = (const float*)d_in[11];
    const float* reg_b = (const float*)d_in[12];
    float* out = (float*)d_out;

    __nv_bfloat16 *f0t, *f1t, *f2t, *f3t;
    uint8_t *roi_feats, *h1, *h2, *fc1wq, *fc2wq, *headwq;
    float *headb, *part;
    float *sc80, *boxes, *sboxes;
    cudaGetSymbolAddress((void**)&f0t, g_f0t);
    cudaGetSymbolAddress((void**)&f1t, g_f1t);
    cudaGetSymbolAddress((void**)&f2t, g_f2t);
    cudaGetSymbolAddress((void**)&f3t, g_f3t);
    cudaGetSymbolAddress((void**)&roi_feats, g_roi_feats);
    cudaGetSymbolAddress((void**)&h1, g_h1);
    cudaGetSymbolAddress((void**)&h2, g_h2);
    cudaGetSymbolAddress((void**)&fc1wq, g_fc1w);
    cudaGetSymbolAddress((void**)&fc2wq, g_fc2w);
    cudaGetSymbolAddress((void**)&headwq, g_headw);
    cudaGetSymbolAddress((void**)&headb, g_headb);
    cudaGetSymbolAddress((void**)&part, g_part);
    cudaGetSymbolAddress((void**)&sc80, g_scores80);
    cudaGetSymbolAddress((void**)&boxes, g_boxes);
    cudaGetSymbolAddress((void**)&sboxes, g_sorted_boxes);

    static int smem_set = 0;
    if (!smem_set) {
        cudaFuncSetAttribute(gemm_fp8_splitk_kernel,
                             cudaFuncAttributeMaxDynamicSharedMemorySize, GEMM_SMEM);
        smem_set = 1;
    }

    prep_kernel<<<PREP_TOTAL, 256>>>(f0, f1, f2, f3, f0t, f1t, f2t, f3t,
                                     fc1_w, fc1wq, fc2_w, fc2wq,
                                     cls_w, reg_w, cls_b, reg_b, headwq, headb);

    roi_align_kernel<<<N_PROP, 128>>>(f0t, f1t, f2t, f3t, props, roi_feats);

    // fc1: K=12544 fp8, Kc=3136 (49 k-tiles)
    gemm_fp8_splitk_kernel<<<dim3(FC / 128, (N_PROP + 127) / 128, SPLITK), 512, GEMM_SMEM>>>(
        roi_feats, fc1wq, part, N_PROP, FC, DFEAT / SPLITK, DFEAT);
    reduce_k_kernel<<<(N_PROP * FC + 255) / 256, 256>>>(part, fc1_b, h1, N_PROP, FC);

    // fc2: K=1024, Kc=256 (4 k-tiles)
    gemm_fp8_splitk_kernel<<<dim3(FC / 128, (N_PROP + 127) / 128, SPLITK), 512, GEMM_SMEM>>>(
        h1, fc2wq, part, N_PROP, FC, FC / SPLITK, FC);
    reduce_k_kernel<<<(N_PROP * FC + 255) / 256, 256>>>(part, fc2_b, h2, N_PROP, FC);

    // head: N=401, K=1024 — reduce fused into head_kernel
    gemm_fp8_splitk_kernel<<<dim3((NHEAD + 127) / 128, (N_PROP + 127) / 128, SPLITK), 512, GEMM_SMEM>>>(
        h2, headwq, part, N_PROP, NHEAD, FC / SPLITK, FC);

    head_kernel<<<N_PROP, 128>>>(part, headb, props, sc80, boxes);
    nms_kernel<<<NUM_CLASSES, 256>>>(sc80, boxes, sboxes);
    topk_kernel<<<1, 256>>>(sboxes, out, out_size);
}

// round 13
// speedup vs baseline: 1.1024x; 1.1024x over previous
#include <cuda_runtime.h>
#include <cuda_bf16.h>
#include <math.h>
#include <float.h>
#include <stdint.h>

#define NUM_CLASSES 80
#define N_PROP 1000
#define CCH 256
#define ROI 7
#define DFEAT (CCH * ROI * ROI)   // 12544
#define FC 1024
#define NHEAD 401
#define SCORE_THR 0.05f
#define IOU_THR 0.5f
#define MAX_DET 100
#define MAX_RATIO 4.135166556742356f
#define SPLITK 4

// ---------------- device scratch ----------------
__device__ __nv_bfloat16 g_f0t[200 * 336 * CCH];
__device__ __nv_bfloat16 g_f1t[100 * 168 * CCH];
__device__ __nv_bfloat16 g_f2t[50 * 84 * CCH];
__device__ __nv_bfloat16 g_f3t[25 * 42 * CCH];

__device__ __nv_bfloat16 g_roi_feats[N_PROP * DFEAT];
__device__ __nv_bfloat16 g_h1[N_PROP * FC];
__device__ __nv_bfloat16 g_h2[N_PROP * FC];
__device__ __nv_bfloat16 g_fc1w[FC * DFEAT];
__device__ __nv_bfloat16 g_fc2w[FC * FC];
__device__ __nv_bfloat16 g_headw[NHEAD * FC];
__device__ float g_headb[NHEAD];
__device__ float g_part[SPLITK * N_PROP * FC];

__device__ float g_scores80[N_PROP * NUM_CLASSES];
__device__ float g_boxes[N_PROP * NUM_CLASSES * 4];
__device__ float g_sorted_boxes[NUM_CLASSES * N_PROP * 4];

__device__ int g_ncand;
__device__ float g_cand_v[NUM_CLASSES * N_PROP];
__device__ int   g_cand_i[NUM_CLASSES * N_PROP];

// ---------------- fused prep ----------------
#define PREP_T0 22320
#define PREP_T1 34864
#define PREP_T2 35888
#define PREP_TOTAL 37492

__global__ void prep_kernel(const float* __restrict__ f0,
                            const float* __restrict__ f1,
                            const float* __restrict__ f2,
                            const float* __restrict__ f3,
                            __nv_bfloat16* __restrict__ o0,
                            __nv_bfloat16* __restrict__ o1,
                            __nv_bfloat16* __restrict__ o2,
                            __nv_bfloat16* __restrict__ o3,
                            const float* __restrict__ fc1_w,
                            __nv_bfloat16* __restrict__ fc1wb,
                            const float* __restrict__ fc2_w,
                            __nv_bfloat16* __restrict__ fc2wb,
                            const float* __restrict__ cls_w,
                            const float* __restrict__ reg_w,
                            const float* __restrict__ cls_b,
                            const float* __restrict__ reg_b,
                            __nv_bfloat16* __restrict__ headwb,
                            float* __restrict__ headb) {
    const int b = blockIdx.x;
    const int tid = threadIdx.x;

    if (b < PREP_T0) {
        __shared__ float t[32][33];
        int bt = b >> 3;
        int c0 = (b & 7) * 32;
        const float* in; __nv_bfloat16* out; int HW; int tile;
        if (bt < 2100)      { in = f0; out = o0; HW = 67200; tile = bt; }
        else if (bt < 2625) { in = f1; out = o1; HW = 16800; tile = bt - 2100; }
        else if (bt < 2757) { in = f2; out = o2; HW = 4200;  tile = bt - 2625; }
        else                { in = f3; out = o3; HW = 1050;  tile = bt - 2757; }
        int hw0 = tile * 32;
        int tx = tid & 31, ty = tid >> 5;
        int x = hw0 + tx;
        #pragma unroll
        for (int i = 0; i < 32; i += 8) {
            int c = c0 + ty + i;
            if (x < HW) t[ty + i][tx] = in[(size_t)c * HW + x];
        }
        __syncthreads();
        int co = c0 + tx;
        #pragma unroll
        for (int i = 0; i < 32; i += 8) {
            int xo = hw0 + ty + i;
            if (xo < HW)
                out[(size_t)xo * CCH + co] = __float2bfloat16(t[tx][ty + i]);
        }
    } else if (b < PREP_T1) {
        int i = (b - PREP_T0) * 256 + tid;
        float4 v = ((const float4*)fc1_w)[i];
        ((__nv_bfloat162*)fc1wb)[2 * i] = __floats2bfloat162_rn(v.x, v.y);
        ((__nv_bfloat162*)fc1wb)[2 * i + 1] = __floats2bfloat162_rn(v.z, v.w);
    } else if (b < PREP_T2) {
        int i = (b - PREP_T1) * 256 + tid;
        float4 v = ((const float4*)fc2_w)[i];
        ((__nv_bfloat162*)fc2wb)[2 * i] = __floats2bfloat162_rn(v.x, v.y);
        ((__nv_bfloat162*)fc2wb)[2 * i + 1] = __floats2bfloat162_rn(v.z, v.w);
    } else {
        int i = (b - PREP_T2) * 256 + tid;
        const int total = NHEAD * FC;
        if (i < total) {
            int r = i >> 10, k = i & 1023;
            float v = (r < 81) ? cls_w[r * FC + k] : reg_w[(r - 81) * FC + k];
            headwb[i] = __float2bfloat16(v);
        }
        if (i < NHEAD) headb[i] = (i < 81) ? cls_b[i] : reg_b[i - 81];
    }
}

// ---------------- RoI Align ----------------
__global__ void roi_align_kernel(const __nv_bfloat16* __restrict__ f0,
                                 const __nv_bfloat16* __restrict__ f1,
                                 const __nv_bfloat16* __restrict__ f2,
                                 const __nv_bfloat16* __restrict__ f3,
                                 const float* __restrict__ props,
                                 __nv_bfloat16* __restrict__ out) {
    const int n = blockIdx.x;
    const int tid = threadIdx.x;

    __shared__ int sx0[14], sx1[14], sy0[14], sy1[14];
    __shared__ float slx[14], sly[14];
    __shared__ int svx[14], svy[14];

    float px1 = props[n * 4 + 0];
    float py1 = props[n * 4 + 1];
    float px2 = props[n * 4 + 2];
    float py2 = props[n * 4 + 3];
    float w = px2 - px1, h = py2 - py1;
    float sz = sqrtf(fmaxf(w * h, 1e-6f));
    int lvl = (int)floorf(log2f(sz / 56.0f + 1e-6f));
    lvl = lvl < 0 ? 0 : (lvl > 3 ? 3 : lvl);

    const __nv_bfloat16* feat;
    int H, W;
    if (lvl == 0) { feat = f0; H = 200; W = 336; }
    else if (lvl == 1) { feat = f1; H = 100; W = 168; }
    else if (lvl == 2) { feat = f2; H = 50; W = 84; }
    else { feat = f3; H = 25; W = 42; }
    float scale = 1.0f / (float)(4 << lvl);

    if (tid < 14) {
        int i = tid;
        float pt = ((float)i + 0.5f) / 14.0f;
        {
            float xs = px1 * scale - 0.5f + pt * (w * scale);
            float fx = floorf(xs);
            int x0 = (int)fx; x0 = x0 < 0 ? 0 : (x0 > W - 1 ? W - 1 : x0);
            int x1i = x0 + 1; x1i = x1i > W - 1 ? W - 1 : x1i;
            sx0[i] = x0; sx1[i] = x1i;
            slx[i] = xs - fx;
            svx[i] = (xs >= -1.0f && xs <= (float)W) ? 1 : 0;
        }
        {
            float ys = py1 * scale - 0.5f + pt * (h * scale);
            float fy = floorf(ys);
            int y0 = (int)fy; y0 = y0 < 0 ? 0 : (y0 > H - 1 ? H - 1 : y0);
            int y1i = y0 + 1; y1i = y1i > H - 1 ? H - 1 : y1i;
            sy0[i] = y0; sy1[i] = y1i;
            sly[i] = ys - fy;
            svy[i] = (ys >= -1.0f && ys <= (float)H) ? 1 : 0;
        }
    }
    __syncthreads();

    const __nv_bfloat162* feat2 = (const __nv_bfloat162*)feat;
    __nv_bfloat16* op0 = out + (size_t)n * DFEAT + (size_t)(2 * tid) * (ROI * ROI);
    __nv_bfloat16* op1 = op0 + (ROI * ROI);

    #pragma unroll
    for (int py = 0; py < ROI; py++) {
        #pragma unroll
        for (int px = 0; px < ROI; px++) {
            float acc0 = 0.0f, acc1 = 0.0f;
            #pragma unroll
            for (int sy = 0; sy < 2; sy++) {
                int iy = py * 2 + sy;
                int y0 = sy0[iy], y1v = sy1[iy];
                float ly = sly[iy];
                int vy = svy[iy];
                #pragma unroll
                for (int sxs = 0; sxs < 2; sxs++) {
                    int ix = px * 2 + sxs;
                    if (vy && svx[ix]) {
                        int x0 = sx0[ix], x1v = sx1[ix];
                        float lx = slx[ix];
                        float2 v00 = __bfloat1622float2(feat2[((size_t)(y0 * W + x0) << 7) + tid]);
                        float2 v01 = __bfloat1622float2(feat2[((size_t)(y0 * W + x1v) << 7) + tid]);
                        float2 v10 = __bfloat1622float2(feat2[((size_t)(y1v * W + x0) << 7) + tid]);
                        float2 v11 = __bfloat1622float2(feat2[((size_t)(y1v * W + x1v) << 7) + tid]);
                        float wy0 = 1.0f - ly, wx0 = 1.0f - lx;
                        acc0 += wy0 * (wx0 * v00.x + lx * v01.x) + ly * (wx0 * v10.x + lx * v11.x);
                        acc1 += wy0 * (wx0 * v00.y + lx * v01.y) + ly * (wx0 * v10.y + lx * v11.y);
                    }
                }
            }
            op0[py * ROI + px] = __float2bfloat16(acc0 * 0.25f);
            op1[py * ROI + px] = __float2bfloat16(acc1 * 0.25f);
        }
    }
}

// ---------------- pipelined bf16 mma GEMM: cp.async, BK=64, 3-stage -------
__device__ __forceinline__ void mma16816(float* c, const uint32_t* a, const uint32_t* b) {
    asm volatile(
        "mma.sync.aligned.m16n8k16.row.col.f32.bf16.bf16.f32 "
        "{%0,%1,%2,%3},{%4,%5,%6,%7},{%8,%9},{%0,%1,%2,%3};"
        : "+f"(c[0]), "+f"(c[1]), "+f"(c[2]), "+f"(c[3])
        : "r"(a[0]), "r"(a[1]), "r"(a[2]), "r"(a[3]), "r"(b[0]), "r"(b[1]));
}

__device__ __forceinline__ void ldmx4(uint32_t* r, uint32_t addr) {
    asm volatile("ldmatrix.sync.aligned.m8n8.x4.shared.b16 {%0,%1,%2,%3}, [%4];"
                 : "=r"(r[0]), "=r"(r[1]), "=r"(r[2]), "=r"(r[3]) : "r"(addr));
}

__device__ __forceinline__ void cp16(uint32_t dst, const void* src, int valid) {
    int sz = valid ? 16 : 0;
    asm volatile("cp.async.cg.shared.global [%0], [%1], 16, %2;"
                 :: "r"(dst), "l"(src), "r"(sz));
}

#define LDAPAD 72                 // 64 data + 8 pad bf16 per row; 144B stride
#define TBK 64                    // bf16 elements per k-tile
#define STAGE_E (256 * LDAPAD)    // A(128 rows) + B(128 rows), elems
#define NSTAGE 3
#define GEMM_SMEM (NSTAGE * STAGE_E * 2)   // 110592 B

__global__ __launch_bounds__(512, 2)
void gemm_bf16_splitk_kernel(const __nv_bfloat16* __restrict__ Afull,
                             const __nv_bfloat16* __restrict__ Bfull,
                             float* __restrict__ Cpart,
                             int M, int N, int Kc, int lda) {
    extern __shared__ __nv_bfloat16 smem[];

    const int tid = threadIdx.x;
    const int warp = tid >> 5, lane = tid & 31;
    const int wm = warp >> 2, wn = warp & 3;
    const int g = lane >> 2, tg = lane & 3;
    const int m0 = blockIdx.y * 128, n0 = blockIdx.x * 128;
    const int z = blockIdx.z;

    const __nv_bfloat16* A = Afull + (size_t)z * Kc;
    const __nv_bfloat16* B = Bfull + (size_t)z * Kc;

    const int row = tid >> 2;            // 0..127
    const int kc = (tid & 3) * 16;       // elems 0,16,32,48

    float acc[2][4][4];
    #pragma unroll
    for (int i = 0; i < 2; i++)
        #pragma unroll
        for (int j = 0; j < 4; j++)
            #pragma unroll
            for (int q = 0; q < 4; q++) acc[i][j][q] = 0.0f;

    const uint32_t smem_u32 = (uint32_t)__cvta_generic_to_shared(smem);
    const uint32_t dA = smem_u32 + (uint32_t)((row * LDAPAD + kc) * 2);
    const uint32_t dB = dA + (uint32_t)(128 * LDAPAD * 2);
    const int a_row_l = wm * 32 + (lane & 15);
    const int a_col_l = (lane >> 4) * 8;
    const uint32_t aadr = smem_u32 + (uint32_t)((a_row_l * LDAPAD + a_col_l) * 2);
    const int b_row_l = wn * 32 + (lane & 7) + ((lane >> 4) << 3);
    const int b_col_l = ((lane >> 3) & 1) * 8;
    const uint32_t badr = smem_u32 + (uint32_t)((128 * LDAPAD + b_row_l * LDAPAD + b_col_l) * 2);

    const int ar_ok = (m0 + row) < M;
    const int br_ok = (n0 + row) < N;
    const __nv_bfloat16* aSrcBase = A + (size_t)(m0 + row) * lda + kc;
    const __nv_bfloat16* bSrcBase = B + (size_t)(n0 + row) * lda + kc;

    const int nIter = Kc / TBK;

    // prologue: tiles 0,1
    #pragma unroll
    for (int t = 0; t < 2; t++) {
        if (t < nIter) {
            uint32_t so = (uint32_t)(t * STAGE_E * 2);
            cp16(dA + so, aSrcBase + t * TBK, ar_ok);
            cp16(dA + so + 16, aSrcBase + t * TBK + 8, ar_ok);
            cp16(dB + so, bSrcBase + t * TBK, br_ok);
            cp16(dB + so + 16, bSrcBase + t * TBK + 8, br_ok);
        }
        asm volatile("cp.async.commit_group;");
    }

    int st = 0;
    for (int it = 0; it < nIter; it++) {
        asm volatile("cp.async.wait_group 1;");
        __syncthreads();

        const uint32_t so = (uint32_t)(st * STAGE_E * 2);
        #pragma unroll
        for (int ks = 0; ks < 4; ks++) {
            const uint32_t koff = so + (uint32_t)(ks * 32);   // 16 bf16 = 32B
            uint32_t af[2][4], bfr[2][4];
            ldmx4(af[0], aadr + koff);
            ldmx4(af[1], aadr + koff + (uint32_t)(16 * LDAPAD * 2));
            ldmx4(bfr[0], badr + koff);
            ldmx4(bfr[1], badr + koff + (uint32_t)(16 * LDAPAD * 2));
            #pragma unroll
            for (int mt = 0; mt < 2; mt++)
                #pragma unroll
                for (int nt = 0; nt < 4; nt++)
                    mma16816(acc[mt][nt], af[mt], &bfr[nt >> 1][(nt & 1) * 2]);
        }

        if (it + 2 < nIter) {
            int st2 = st + 2; if (st2 >= NSTAGE) st2 -= NSTAGE;
            const uint32_t so2 = (uint32_t)(st2 * STAGE_E * 2);
            cp16(dA + so2, aSrcBase + (it + 2) * TBK, ar_ok);
            cp16(dA + so2 + 16, aSrcBase + (it + 2) * TBK + 8, ar_ok);
            cp16(dB + so2, bSrcBase + (it + 2) * TBK, br_ok);
            cp16(dB + so2 + 16, bSrcBase + (it + 2) * TBK + 8, br_ok);
        }
        asm volatile("cp.async.commit_group;");

        if (++st == NSTAGE) st = 0;
    }

    float* Cp = Cpart + (size_t)z * M * N;
    #pragma unroll
    for (int mt = 0; mt < 2; mt++) {
        #pragma unroll
        for (int nt = 0; nt < 4; nt++) {
            int n = n0 + wn * 32 + nt * 8 + tg * 2;
            if (n >= N) continue;
            #pragma unroll
            for (int rh = 0; rh < 2; rh++) {
                int m = m0 + wm * 32 + mt * 16 + g + rh * 8;
                if (m >= M) continue;
                Cp[(size_t)m * N + n] = acc[mt][nt][rh * 2 + 0];
                if (n + 1 < N) Cp[(size_t)m * N + n + 1] = acc[mt][nt][rh * 2 + 1];
            }
        }
    }
}

// ---------------- split-K reduce (vectorized, N % 4 == 0) ----------------
__global__ void reduce_k_kernel(const float* __restrict__ part,
                                const float* __restrict__ bias,
                                __nv_bfloat16* __restrict__ out,
                                int M, int N) {
    int i4 = blockIdx.x * blockDim.x + threadIdx.x;
    int tot4 = M * N / 4;
    if (i4 >= tot4) return;
    int n4 = i4 % (N / 4);
    float4 v = ((const float4*)part)[i4];
    #pragma unroll
    for (int s = 1; s < SPLITK; s++) {
        float4 p = ((const float4*)part)[(size_t)s * tot4 + i4];
        v.x += p.x; v.y += p.y; v.z += p.z; v.w += p.w;
    }
    float4 b = ((const float4*)bias)[n4];
    v.x = fmaxf(v.x + b.x, 0.0f);
    v.y = fmaxf(v.y + b.y, 0.0f);
    v.z = fmaxf(v.z + b.z, 0.0f);
    v.w = fmaxf(v.w + b.w, 0.0f);
    ((__nv_bfloat162*)out)[2 * i4] = __floats2bfloat162_rn(v.x, v.y);
    ((__nv_bfloat162*)out)[2 * i4 + 1] = __floats2bfloat162_rn(v.z, v.w);
}

// ---------------- softmax + delta2bbox (reads head partials, fused reduce) -
__global__ void head_kernel(const float* __restrict__ part,
                            const float* __restrict__ headb,
                            const float* __restrict__ props,
                            float* __restrict__ scores80,
                            float* __restrict__ boxes) {
    const int n = blockIdx.x;
    const int tid = threadIdx.x;
    if (n == 0 && tid == 0) g_ncand = 0;

    const int TOT = N_PROP * NHEAD;

    __shared__ float sv[81];
    __shared__ float red[128];

    float v = -FLT_MAX;
    if (tid < 81) {
        v = headb[tid];
        #pragma unroll
        for (int s = 0; s < SPLITK; s++)
            v += part[(size_t)s * TOT + (size_t)n * NHEAD + tid];
        sv[tid] = v;
    }
    red[tid] = v;
    __syncthreads();
    for (int s = 64; s > 0; s >>= 1) {
        if (tid < s) red[tid] = fmaxf(red[tid], red[tid + s]);
        __syncthreads();
    }
    float mx = red[0];
    __syncthreads();
    float e = (tid < 81) ? expf(sv[tid] - mx) : 0.0f;
    red[tid] = e;
    __syncthreads();
    for (int s = 64; s > 0; s >>= 1) {
        if (tid < s) red[tid] += red[tid + s];
        __syncthreads();
    }
    float sum = red[0];

    if (tid < NUM_CLASSES) {
        scores80[n * NUM_CLASSES + tid] = e / sum;

        float rp[4];
        #pragma unroll
        for (int q = 0; q < 4; q++) {
            int idx = 81 + tid * 4 + q;
            float r = headb[idx];
            #pragma unroll
            for (int s = 0; s < SPLITK; s++)
                r += part[(size_t)s * TOT + (size_t)n * NHEAD + idx];
            rp[q] = r;
        }
        float dx = rp[0] * 0.1f;
        float dy = rp[1] * 0.1f;
        float dw = fminf(fmaxf(rp[2] * 0.2f, -MAX_RATIO), MAX_RATIO);
        float dh = fminf(fmaxf(rp[3] * 0.2f, -MAX_RATIO), MAX_RATIO);
        float p0 = props[n * 4 + 0], p1 = props[n * 4 + 1];
        float p2 = props[n * 4 + 2], p3 = props[n * 4 + 3];
        float pcx = (p0 + p2) * 0.5f;
        float pcy = (p1 + p3) * 0.5f;
        float pw = p2 - p0, ph = p3 - p1;
        float gw = pw * expf(dw);
        float gh = ph * expf(dh);
        float gx = pcx + pw * dx;
        float gy = pcy + ph * dy;
        float* bp = boxes + ((size_t)n * NUM_CLASSES + tid) * 4;
        bp[0] = gx - gw * 0.5f;
        bp[1] = gy - gh * 0.5f;
        bp[2] = gx + gw * 0.5f;
        bp[3] = gy + gh * 0.5f;
    }
}

// ---------------- per-class NMS, appends candidates ----------------
__global__ void nms_kernel(const float* __restrict__ scores80,
                           const float* __restrict__ boxesAll,
                           float* __restrict__ sortedBoxes) {
    const int c = blockIdx.x;
    const int tid = threadIdx.x;
    const int NT = 256;

    __shared__ float skey[1024];
    __shared__ int sidx[1024];
    __shared__ float4 sbox[N_PROP];
    __shared__ float sarea[N_PROP];
    __shared__ unsigned char keep[N_PROP];
    __shared__ float redmax[NT];

    float mv = -FLT_MAX;
    for (int j = tid; j < N_PROP; j += NT) {
        float s = scores80[j * NUM_CLASSES + c];
        mv = fmaxf(mv, s);
        skey[j] = s;
    }
    redmax[tid] = mv;
    __syncthreads();
    for (int s = NT / 2; s > 0; s >>= 1) {
        if (tid < s) redmax[tid] = fmaxf(redmax[tid], redmax[tid + s]);
        __syncthreads();
    }
    if (redmax[0] <= SCORE_THR) return;

    for (int j = tid; j < 1024; j += NT) {
        if (j >= N_PROP) skey[j] = -FLT_MAX;
        sidx[j] = j;
    }

    for (int k = 2; k <= 1024; k <<= 1) {
        for (int j = k >> 1; j > 0; j >>= 1) {
            __syncthreads();
            for (int i = tid; i < 1024; i += NT) {
                int ixj = i ^ j;
                if (ixj > i) {
                    float si = skey[i], sx = skey[ixj];
                    int ii = sidx[i], ix = sidx[ixj];
                    bool x_first = (sx > si) || (sx == si && ix < ii);
                    bool up = ((i & k) == 0);
                    if (up ? x_first : !x_first) {
                        skey[i] = sx; skey[ixj] = si;
                        sidx[i] = ix; sidx[ixj] = ii;
                    }
                }
            }
        }
    }
    __syncthreads();

    for (int j = tid; j < N_PROP; j += NT) {
        int oi = sidx[j];
        float4 b = *(const float4*)&boxesAll[((size_t)oi * NUM_CLASSES + c) * 4];
        sbox[j] = b;
        sarea[j] = fmaxf(b.z - b.x, 0.0f) * fmaxf(b.w - b.y, 0.0f);
        keep[j] = (skey[j] > SCORE_THR) ? 1 : 0;
    }
    __syncthreads();

    for (int i = 0; i < N_PROP; i++) {
        if (skey[i] <= SCORE_THR) break;
        __syncthreads();
        if (keep[i]) {
            float4 bi = sbox[i];
            float ai = sarea[i];
            for (int j = i + 1 + tid; j < N_PROP; j += NT) {
                if (!keep[j]) continue;
                float4 bj = sbox[j];
                float iw = fmaxf(fminf(bi.z, bj.z) - fmaxf(bi.x, bj.x), 0.0f);
                float ih = fmaxf(fminf(bi.w, bj.w) - fmaxf(bi.y, bj.y), 0.0f);
                float inter = iw * ih;
                float iou = inter / fmaxf(ai + sarea[j] - inter, 1e-8f);
                if (iou > IOU_THR) keep[j] = 0;
            }
        }
    }
    __syncthreads();

    for (int j = tid; j < N_PROP; j += NT) {
        *(float4*)&sortedBoxes[((size_t)c * N_PROP + j) * 4] = sbox[j];
        if (keep[j]) {
            int p = atomicAdd(&g_ncand, 1);
            g_cand_v[p] = skey[j];
            g_cand_i[p] = c * N_PROP + j;
        }
    }
}

// ---------------- top-k + output assembly ----------------
__global__ void topk_kernel(const float* __restrict__ sortedBoxes,
                            float* __restrict__ out, int out_size) {
    const int tid = threadIdx.x;
    const int NT = 256;
    const int nc = g_ncand;
    const int nsel = nc < MAX_DET ? nc : MAX_DET;

    __shared__ float rv[NT];
    __shared__ int ri[NT];
    __shared__ int rs[NT];
    __shared__ float topv[MAX_DET];
    __shared__ int topi[MAX_DET];

    for (int k = tid; k < MAX_DET; k += NT) { topv[k] = -FLT_MAX; topi[k] = 0; }
    __syncthreads();

    for (int sel = 0; sel < nsel; sel++) {
        float bv = -FLT_MAX;
        int bi = 0x7fffffff, bs = -1;
        for (int j = tid; j < nc; j += NT) {
            float v = g_cand_v[j];
            int fi = g_cand_i[j];
            if (v > bv || (v == bv && fi < bi)) { bv = v; bi = fi; bs = j; }
        }
        rv[tid] = bv; ri[tid] = bi; rs[tid] = bs;
        __syncthreads();
        for (int s = NT / 2; s > 0; s >>= 1) {
            if (tid < s) {
                if (rv[tid + s] > rv[tid] ||
                    (rv[tid + s] == rv[tid] && ri[tid + s] < ri[tid])) {
                    rv[tid] = rv[tid + s]; ri[tid] = ri[tid + s]; rs[tid] = rs[tid + s];
                }
            }
            __syncthreads();
        }
        if (tid == 0) {
            topv[sel] = rv[0];
            topi[sel] = ri[0];
            if (rs[0] >= 0) g_cand_v[rs[0]] = -FLT_MAX;
        }
        __syncthreads();
    }

    if (tid == 0) {
        int nd = 0;
        for (int k = 0; k < MAX_DET; k++)
            if (topv[k] > 0.0f) nd++;
        if (out_size > 0) out[0] = (float)nd;
    }
    __syncthreads();

    for (int k = tid; k < MAX_DET; k += NT) {
        bool valid = topv[k] > 0.0f;
        int oi = topi[k];
        float b0 = 0.f, b1 = 0.f, b2 = 0.f, b3 = 0.f;
        if (valid) {
            const float* bp = &sortedBoxes[(size_t)oi * 4];
            b0 = bp[0]; b1 = bp[1]; b2 = bp[2]; b3 = bp[3];
        }
        if (1 + k * 4 + 3 < out_size) {
            out[1 + k * 4 + 0] = b0;
            out[1 + k * 4 + 1] = b1;
            out[1 + k * 4 + 2] = b2;
            out[1 + k * 4 + 3] = b3;
        }
        if (401 + k < out_size) out[401 + k] = valid ? topv[k] : 0.0f;
        if (501 + k < out_size) out[501 + k] = valid ? (float)(oi / N_PROP) : -1.0f;
    }
    for (int i = 601 + tid; i < out_size; i += NT) out[i] = 0.0f;
}

// ---------------- launch ----------------
extern "C" void kernel_launch(void* const* d_in, const int* in_sizes, int n_in,
                              void* d_out, int out_size) {
    const float* f0 = (const float*)d_in[0];
    const float* f1 = (const float*)d_in[1];
    const float* f2 = (const float*)d_in[2];
    const float* f3 = (const float*)d_in[3];
    const float* props = (const float*)d_in[4];
    const float* fc1_w = (const float*)d_in[5];
    const float* fc1_b = (const float*)d_in[6];
    const float* fc2_w = (const float*)d_in[7];
    const float* fc2_b = (const float*)d_in[8];
    const float* cls_w = (const float*)d_in[9];
    const float* cls_b = (const float*)d_in[10];
    const float* reg_w = (const float*)d_in[11];
    const float* reg_b = (const float*)d_in[12];
    float* out = (float*)d_out;

    __nv_bfloat16 *f0t, *f1t, *f2t, *f3t, *roi_feats, *h1, *h2;
    __nv_bfloat16 *fc1wb, *fc2wb, *headwb;
    float *headb, *part;
    float *sc80, *boxes, *sboxes;
    cudaGetSymbolAddress((void**)&f0t, g_f0t);
    cudaGetSymbolAddress((void**)&f1t, g_f1t);
    cudaGetSymbolAddress((void**)&f2t, g_f2t);
    cudaGetSymbolAddress((void**)&f3t, g_f3t);
    cudaGetSymbolAddress((void**)&roi_feats, g_roi_feats);
    cudaGetSymbolAddress((void**)&h1, g_h1);
    cudaGetSymbolAddress((void**)&h2, g_h2);
    cudaGetSymbolAddress((void**)&fc1wb, g_fc1w);
    cudaGetSymbolAddress((void**)&fc2wb, g_fc2w);
    cudaGetSymbolAddress((void**)&headwb, g_headw);
    cudaGetSymbolAddress((void**)&headb, g_headb);
    cudaGetSymbolAddress((void**)&part, g_part);
    cudaGetSymbolAddress((void**)&sc80, g_scores80);
    cudaGetSymbolAddress((void**)&boxes, g_boxes);
    cudaGetSymbolAddress((void**)&sboxes, g_sorted_boxes);

    static int smem_set = 0;
    if (!smem_set) {
        cudaFuncSetAttribute(gemm_bf16_splitk_kernel,
                             cudaFuncAttributeMaxDynamicSharedMemorySize, GEMM_SMEM);
        smem_set = 1;
    }

    prep_kernel<<<PREP_TOTAL, 256>>>(f0, f1, f2, f3, f0t, f1t, f2t, f3t,
                                     fc1_w, fc1wb, fc2_w, fc2wb,
                                     cls_w, reg_w, cls_b, reg_b, headwb, headb);

    roi_align_kernel<<<N_PROP, 128>>>(f0t, f1t, f2t, f3t, props, roi_feats);

    // fc1: Kc=3136 -> 49 k-tiles of 64
    gemm_bf16_splitk_kernel<<<dim3(FC / 128, (N_PROP + 127) / 128, SPLITK), 512, GEMM_SMEM>>>(
        roi_feats, fc1wb, part, N_PROP, FC, DFEAT / SPLITK, DFEAT);
    reduce_k_kernel<<<(N_PROP * FC / 4 + 255) / 256, 256>>>(part, fc1_b, h1, N_PROP, FC);

    // fc2: Kc=256 -> 4 k-tiles
    gemm_bf16_splitk_kernel<<<dim3(FC / 128, (N_PROP + 127) / 128, SPLITK), 512, GEMM_SMEM>>>(
        h1, fc2wb, part, N_PROP, FC, FC / SPLITK, FC);
    reduce_k_kernel<<<(N_PROP * FC / 4 + 255) / 256, 256>>>(part, fc2_b, h2, N_PROP, FC);

    // head: N=401 — reduce fused into head_kernel
    gemm_bf16_splitk_kernel<<<dim3((NHEAD + 127) / 128, (N_PROP + 127) / 128, SPLITK), 512, GEMM_SMEM>>>(
        h2, headwb, part, N_PROP, NHEAD, FC / SPLITK, FC);

    head_kernel<<<N_PROP, 128>>>(part, headb, props, sc80, boxes);
    nms_kernel<<<NUM_CLASSES, 256>>>(sc80, boxes, sboxes);
    topk_kernel<<<1, 256>>>(sboxes, out, out_size);
}